// round 15
// baseline (speedup 1.0000x reference)
#include <cuda_runtime.h>
#include <math.h>

#define BB    64
#define TT    400
#define NN    1024
#define NINC  128
#define NOUTC 32
#define BN    (BB * NN)
#define SPLITK 32
#define NCHUNK 6            // 96 K per GEMM CTA = 6 chunks of 16
#define NCTA  128
#define NTH   512
#define WPITCH 264          // W row pitch (floats), bank-conflict-free (264%32=8)
#define APITCH 72           // act row pitch (floats), bank-conflict-free (72%32=8)
#define BBYTES (16 * WPITCH * 4)          // 16896 per plane per chunk
#define ABYTES (16 * APITCH * 4)          // 4608  per plane per chunk
#define STAGEB (2 * BBYTES + 2 * ABYTES)  // 43008

// ---------------- device scratch -------------------------------------------------
__device__ __align__(128) float g_Wh[4 * 3072 * WPITCH];  // [ot][k][c] tf32-hi
__device__ __align__(128) float g_Wl[4 * 3072 * WPITCH];  // [ot][k][c] tf32-lo
__device__ __align__(128) float g_acth[5 * NN * APITCH];  // [slot][e][b] act hi
__device__ __align__(128) float g_actl[5 * NN * APITCH];  // [slot][e][b] act lo
__device__ __align__(128) float g_inp[TT * BN];
__device__ __align__(128) float g_mem[BN];
__device__ __align__(128) float g_wp[BN];
__device__ __align__(128) float g_outd[2 * BN];
__device__ __align__(128) float g_part[SPLITK * BN];
__device__ __align__(128) float g_r[BB * NOUTC];
__device__ unsigned g_bar;

__device__ __forceinline__ unsigned tf32_hi(float x) {
    unsigned r; asm("cvt.rna.tf32.f32 %0, %1;" : "=r"(r) : "f"(x)); return r;
}
#define MMA_TF32(c, a, b0, b1) \
    asm("mma.sync.aligned.m16n8k8.row.col.f32.tf32.tf32.f32 " \
        "{%0,%1,%2,%3},{%4,%5,%6,%7},{%8,%9},{%0,%1,%2,%3};" \
        : "+f"((c)[0]), "+f"((c)[1]), "+f"((c)[2]), "+f"((c)[3]) \
        : "r"((a)[0]), "r"((a)[1]), "r"((a)[2]), "r"((a)[3]), "r"(b0), "r"(b1))

__device__ __forceinline__ unsigned smem_u32(const void* p) {
    return (unsigned)__cvta_generic_to_shared(p);
}
__device__ __forceinline__ void bulkcp(unsigned sdst, const void* gsrc,
                                       unsigned bytes, unsigned mb) {
    asm volatile(
        "cp.async.bulk.shared::cluster.global.mbarrier::complete_tx::bytes "
        "[%0], [%1], %2, [%3];"
        :: "r"(sdst), "l"(gsrc), "r"(bytes), "r"(mb) : "memory");
}
// HW-sleep wait (ptx_helpers pattern): try_wait with suspend-time hint, retry loop
__device__ __forceinline__ void mb_wait(unsigned mb, unsigned parity) {
    unsigned done;
    asm volatile(
        "{\n\t.reg .pred p;\n\t"
        "mbarrier.try_wait.parity.acquire.cta.shared::cta.b64 p, [%1], %2;\n\t"
        "selp.b32 %0, 1, 0, p;\n\t}"
        : "=r"(done) : "r"(mb), "r"(parity) : "memory");
    if (!done) {
        asm volatile(
            "{\n\t.reg .pred P1;\n\t"
            "WAIT_LOOP_%=:\n\t"
            "mbarrier.try_wait.parity.acquire.cta.shared::cta.b64 P1, [%0], %1, 0x989680;\n\t"
            "@P1 bra.uni WAIT_DONE_%=;\n\t"
            "bra.uni WAIT_LOOP_%=;\n\t"
            "WAIT_DONE_%=:\n\t}"
            :: "r"(mb), "r"(parity) : "memory");
    }
}

// ---------------- zero state + barrier -------------------------------------------
__global__ void k_init() {
    int i = blockIdx.x * 256 + threadIdx.x;
    const int st = 64 * 256;
    for (int j = i; j < BN; j += st) { g_mem[j] = 0.f; g_wp[j] = 0.f; }
    for (int j = i; j < 2 * BN; j += st) g_outd[j] = 0.f;
    for (int j = i; j < 5 * NN * APITCH; j += st) { g_acth[j] = 0.f; g_actl[j] = 0.f; }
    for (int j = i; j < BB * NOUTC; j += st) g_r[j] = 0.f;
    if (i == 0) g_bar = 0u;
}

// ---------------- W prep: reorder to [ot][k][264] + tf32 hi/lo split -------------
__global__ void k_prep(const float* __restrict__ w, const float* __restrict__ ws,
                       const float* __restrict__ dmap) {
    int i = blockIdx.x * 256 + threadIdx.x;          // over [d][e][o]
    int eo = i & (NN * NN - 1);
    int d = i >> 20, e = eo >> 10, o = eo & (NN - 1);
    float v = dmap[i] * (ws[e] * fabsf(w[eo]));
    unsigned h = tf32_hi(v);
    float hf = __uint_as_float(h);
    int idx = (o >> 8) * (3072 * WPITCH) + (d * NN + e) * WPITCH + (o & 255);
    g_Wh[idx] = hf;
    g_Wl[idx] = __uint_as_float(tf32_hi(v - hf));
}

// ------------- input projection (unchanged fp32) ---------------------------------
__global__ __launch_bounds__(256) void k_inp(const float* __restrict__ inputs,
                                             const float* __restrict__ w_in) {
    __shared__ float A_sm[64 * 33];
    __shared__ float W_sm[32 * 64];
    const int mt = blockIdx.x >> 4;
    const int nt = blockIdx.x & 15;
    const int tid = threadIdx.x;
    const int mq = tid >> 4, nq = tid & 15;
    float acc[16];
#pragma unroll
    for (int i = 0; i < 16; i++) acc[i] = 0.f;
    for (int c0 = 0; c0 < NINC; c0 += 32) {
        int kk = tid & 31, rb = tid >> 5;
#pragma unroll
        for (int j = 0; j < 8; j++) {
            int row = rb + 8 * j;
            A_sm[row * 33 + kk] = inputs[row * (TT * NINC) + mt * NINC + c0 + kk];
        }
        int ol = tid & 63, kl = tid >> 6;
#pragma unroll
        for (int j = 0; j < 8; j++) {
            int k2 = kl + 4 * j;
            W_sm[k2 * 64 + ol] = w_in[(c0 + k2) * NN + nt * 64 + ol];
        }
        __syncthreads();
#pragma unroll
        for (int k2 = 0; k2 < 32; k2++) {
            float4 wv = *(const float4*)&W_sm[k2 * 64 + nq * 4];
            float a0 = A_sm[(mq * 4 + 0) * 33 + k2];
            float a1 = A_sm[(mq * 4 + 1) * 33 + k2];
            float a2 = A_sm[(mq * 4 + 2) * 33 + k2];
            float a3 = A_sm[(mq * 4 + 3) * 33 + k2];
            acc[0]  += a0 * wv.x; acc[1]  += a0 * wv.y; acc[2]  += a0 * wv.z; acc[3]  += a0 * wv.w;
            acc[4]  += a1 * wv.x; acc[5]  += a1 * wv.y; acc[6]  += a1 * wv.z; acc[7]  += a1 * wv.w;
            acc[8]  += a2 * wv.x; acc[9]  += a2 * wv.y; acc[10] += a2 * wv.z; acc[11] += a2 * wv.w;
            acc[12] += a3 * wv.x; acc[13] += a3 * wv.y; acc[14] += a3 * wv.z; acc[15] += a3 * wv.w;
        }
        __syncthreads();
    }
#pragma unroll
    for (int i = 0; i < 4; i++) {
        float4 v = make_float4(acc[i * 4], acc[i * 4 + 1], acc[i * 4 + 2], acc[i * 4 + 3]);
        *(float4*)&g_inp[mt * BN + (mq * 4 + i) * NN + nt * 64 + nq * 4] = v;
    }
}

// -------- grid barrier (proven R9/R11/R12/R13) -----------------------------------
__device__ __forceinline__ void gbar(unsigned& target) {
    __syncthreads();
    if (threadIdx.x == 0) {
        __threadfence();
        atomicAdd(&g_bar, 1u);
        target += NCTA;
        unsigned v;
        asm volatile("ld.acquire.gpu.u32 %0, [%1];" : "=r"(v) : "l"(&g_bar) : "memory");
        while (v < target) {
            __nanosleep(32);
            asm volatile("ld.acquire.gpu.u32 %0, [%1];" : "=r"(v) : "l"(&g_bar) : "memory");
        }
    }
    __syncthreads();
}

// ---------------- persistent T-loop ----------------------------------------------
__global__ __launch_bounds__(NTH, 1) void k_loop(const float* __restrict__ p,
                                                 const float* __restrict__ w_out,
                                                 float* __restrict__ out) {
    extern __shared__ float dsm[];          // 2 stages x STAGEB bytes
    __shared__ float red[NTH];
    __shared__ __align__(8) unsigned long long mbarS[2];
    const int tid = threadIdx.x;
    const int bid = blockIdx.x;
    const int ot = bid >> 5, kbs = bid & 31;
    const int obase = ot * 256;
    const int lane = tid & 31, wid = tid >> 5;
    const int g = lane >> 2, ig = lane & 3;
    const int mw = wid & 1;                 // 2 m-groups (32 rows each)
    const int nw = wid >> 1;                // 8 n-groups (32 cols each)
    const unsigned mb0 = smem_u32(&mbarS[0]);
    const unsigned mb1 = mb0 + 8;
    const unsigned sbase = smem_u32(dsm);
    unsigned target = 0;
    unsigned pc0 = 0, pc1 = 0;

    if (tid == 0) {
        asm volatile("mbarrier.init.shared.b64 [%0], 1;" :: "r"(mb0) : "memory");
        asm volatile("mbarrier.init.shared.b64 [%0], 1;" :: "r"(mb1) : "memory");
    }
    __syncthreads();

    for (int t = 0; t <= TT; ++t) {
        // ================= phase A: GEMM(t) via 3xTF32 mma.sync + bulk copies ====
        if (t < TT) {
            const int s1 = (t + 4) % 5, s2 = (t + 3) % 5, s4 = (t + 1) % 5;
            float c[2][4][4];
#pragma unroll
            for (int mt = 0; mt < 2; mt++)
#pragma unroll
                for (int nb = 0; nb < 4; nb++)
#pragma unroll
                    for (int j = 0; j < 4; j++) c[mt][nb][j] = 0.f;

            auto issue = [&](int cc, int st) {
                int k0 = kbs * 96 + cc * 16;
                int d = k0 >> 10, e0 = k0 & (NN - 1);
                int sl = (d == 0) ? s1 : ((d == 1) ? s2 : s4);
                unsigned sb = sbase + st * STAGEB;
                unsigned mb = st ? mb1 : mb0;
                asm volatile("mbarrier.arrive.expect_tx.shared.b64 _, [%0], %1;"
                             :: "r"(mb), "r"((unsigned)STAGEB) : "memory");
                const float* wsrc = &g_Wh[ot * (3072 * WPITCH) + k0 * WPITCH];
                const float* wsrl = &g_Wl[ot * (3072 * WPITCH) + k0 * WPITCH];
                bulkcp(sb, wsrc, BBYTES, mb);
                bulkcp(sb + BBYTES, wsrl, BBYTES, mb);
                bulkcp(sb + 2 * BBYTES, &g_acth[sl * (NN * APITCH) + e0 * APITCH], ABYTES, mb);
                bulkcp(sb + 2 * BBYTES + ABYTES, &g_actl[sl * (NN * APITCH) + e0 * APITCH], ABYTES, mb);
            };
            if (tid == 0) { issue(0, 0); issue(1, 1); }

            for (int cc = 0; cc < NCHUNK; cc++) {
                const int st = cc & 1;
                mb_wait(st ? mb1 : mb0, (st ? pc1 : pc0) & 1);
                if (st) pc1++; else pc0++;

                const float* Bh = dsm + st * (STAGEB / 4);
                const float* Bl = Bh + 16 * WPITCH;
                const float* Ah = Bh + 2 * 16 * WPITCH;
                const float* Al = Ah + 16 * APITCH;
#pragma unroll
                for (int q = 0; q < 2; q++) {
                    const int kk = q * 8;
                    unsigned ah[2][4], al[2][4];
#pragma unroll
                    for (int mt = 0; mt < 2; mt++) {
                        int r0 = mw * 32 + mt * 16 + g;
                        ah[mt][0] = __float_as_uint(Ah[(kk + ig) * APITCH + r0]);
                        ah[mt][1] = __float_as_uint(Ah[(kk + ig) * APITCH + r0 + 8]);
                        ah[mt][2] = __float_as_uint(Ah[(kk + ig + 4) * APITCH + r0]);
                        ah[mt][3] = __float_as_uint(Ah[(kk + ig + 4) * APITCH + r0 + 8]);
                        al[mt][0] = __float_as_uint(Al[(kk + ig) * APITCH + r0]);
                        al[mt][1] = __float_as_uint(Al[(kk + ig) * APITCH + r0 + 8]);
                        al[mt][2] = __float_as_uint(Al[(kk + ig + 4) * APITCH + r0]);
                        al[mt][3] = __float_as_uint(Al[(kk + ig + 4) * APITCH + r0 + 8]);
                    }
#pragma unroll
                    for (int nb = 0; nb < 4; nb++) {
                        int col = nw * 32 + nb * 8 + g;
                        unsigned bh0 = __float_as_uint(Bh[(kk + ig) * WPITCH + col]);
                        unsigned bh1 = __float_as_uint(Bh[(kk + ig + 4) * WPITCH + col]);
                        unsigned bl0 = __float_as_uint(Bl[(kk + ig) * WPITCH + col]);
                        unsigned bl1 = __float_as_uint(Bl[(kk + ig + 4) * WPITCH + col]);
#pragma unroll
                        for (int mt = 0; mt < 2; mt++) {
                            MMA_TF32(c[mt][nb], ah[mt], bh0, bh1);
                            MMA_TF32(c[mt][nb], ah[mt], bl0, bl1);
                            MMA_TF32(c[mt][nb], al[mt], bh0, bh1);
                        }
                    }
                }
                __syncthreads();                 // all done reading stage st
                if (cc + 2 < NCHUNK && tid == 0) issue(cc + 2, st);
            }
#pragma unroll
            for (int mt = 0; mt < 2; mt++)
#pragma unroll
                for (int nb = 0; nb < 4; nb++) {
                    int col = obase + nw * 32 + nb * 8 + 2 * ig;
                    int r0 = mw * 32 + mt * 16 + g;
                    *(float2*)&g_part[kbs * BN + r0 * NN + col] =
                        make_float2(c[mt][nb][0], c[mt][nb][1]);
                    *(float2*)&g_part[kbs * BN + (r0 + 8) * NN + col] =
                        make_float2(c[mt][nb][2], c[mt][nb][3]);
                }
        }
        gbar(target);

        // ================= phase B: update(t) | readout(t-1) =================
        if (bid < 32) {
            if (t < TT) {
                int i4 = (bid * NTH + tid) * 4;
                int b = i4 >> 10, nb0 = i4 & (NN - 1), sl = t % 5;
                float4 mem  = *(float4*)&g_mem[i4];
                float4 wp   = *(float4*)&g_wp[i4];
                float4 pv   = *(const float4*)&p[nb0];
                float4 inpv = *(float4*)&g_inp[t * BN + i4];
                float4 syn  = make_float4(0.f, 0.f, 0.f, 0.f);
#pragma unroll
                for (int k = 0; k < SPLITK; k++) {   // deterministic fixed-order reduce
                    float4 v = __ldcg((const float4*)&g_part[k * BN + i4]);
                    syn.x += v.x; syn.y += v.y; syn.z += v.z; syn.w += v.w;
                }
                float o0 = mem.x > 1.f ? 1.f : 0.f;
                float o1 = mem.y > 1.f ? 1.f : 0.f;
                float o2 = mem.z > 1.f ? 1.f : 0.f;
                float o3 = mem.w > 1.f ? 1.f : 0.f;

                float av[4] = { o0 * (1.f + wp.x), o1 * (1.f + wp.y),
                                o2 * (1.f + wp.z), o3 * (1.f + wp.w) };
#pragma unroll
                for (int j = 0; j < 4; j++) {        // transposed tf32 hi/lo planes
                    unsigned h = tf32_hi(av[j]);
                    float hf = __uint_as_float(h);
                    int off = sl * (NN * APITCH) + (nb0 + j) * APITCH + b;
                    g_acth[off] = hf;
                    g_actl[off] = __uint_as_float(tf32_hi(av[j] - hf));
                }
                *(float4*)&g_outd[(t & 1) * BN + i4] = make_float4(o0, o1, o2, o3);

                wp.x = 0.99f * wp.x + o0 * pv.x * (1.f + (pv.x < 0.f ? wp.x : 0.f));
                wp.y = 0.99f * wp.y + o1 * pv.y * (1.f + (pv.y < 0.f ? wp.y : 0.f));
                wp.z = 0.99f * wp.z + o2 * pv.z * (1.f + (pv.z < 0.f ? wp.z : 0.f));
                wp.w = 0.99f * wp.w + o3 * pv.w * (1.f + (pv.w < 0.f ? wp.w : 0.f));

                mem.x = 0.95f * mem.x + inpv.x + syn.x - o0;
                mem.y = 0.95f * mem.y + inpv.y + syn.y - o1;
                mem.z = 0.95f * mem.z + inpv.z + syn.z - o2;
                mem.w = 0.95f * mem.w + inpv.w + syn.w - o3;

                *(float4*)&g_wp[i4]  = wp;
                *(float4*)&g_mem[i4] = mem;
                asm volatile("fence.proxy.async;" ::: "memory");  // generic->async proxy order
            }
        } else if (bid < 96 && t > 0) {
            int b = bid - 32;
            int o = tid & 31, ch = tid >> 5;
            const float* ob = &g_outd[((t - 1) & 1) * BN + b * NN];
            float s = 0.f;
            int e0 = ch * 64;
#pragma unroll 4
            for (int e = e0; e < e0 + 64; e++)
                s += __ldcg(&ob[e]) * __ldg(&w_out[e * NOUTC + o]);
            red[tid] = s;
            __syncthreads();
            if (tid < 32) {
                float h = 0.f;
#pragma unroll
                for (int cq = 0; cq < 16; cq++) h += red[cq * 32 + tid];
                float r = 0.95f * g_r[b * NOUTC + tid] + h;
                g_r[b * NOUTC + tid] = r;
                out[b * (TT * NOUTC) + (t - 1) * NOUTC + tid] = r;
            }
            __syncthreads();
        }
        gbar(target);
    }
}

extern "C" void kernel_launch(void* const* d_in, const int* in_sizes, int n_in,
                              void* d_out, int out_size) {
    (void)in_sizes; (void)n_in; (void)out_size;
    const float* inputs = (const float*)d_in[0];
    const float* w      = (const float*)d_in[1];
    const float* w_in   = (const float*)d_in[2];
    const float* w_out  = (const float*)d_in[3];
    const float* ws     = (const float*)d_in[4];
    const float* dmap   = (const float*)d_in[5];
    const float* p      = (const float*)d_in[6];
    float* out = (float*)d_out;

    cudaFuncSetAttribute(k_loop, cudaFuncAttributeMaxDynamicSharedMemorySize,
                         2 * STAGEB);     // idempotent host call; not a stream op
    k_init<<<64, 256>>>();
    k_prep<<<(3 * NN * NN) / 256, 256>>>(w, ws, dmap);
    k_inp<<<TT * 16, 256>>>(inputs, w_in);
    k_loop<<<NCTA, NTH, 2 * STAGEB>>>(p, w_out, out);
}

// round 16
// speedup vs baseline: 1.5827x; 1.5827x over previous
#include <cuda_runtime.h>
#include <cuda_fp16.h>
#include <math.h>

#define BB    64
#define TT    400
#define NN    1024
#define NINC  128
#define NOUTC 32
#define BN    (BB * NN)
#define SPLITK 32
#define NCTA  128
#define NTH   512
// W smem image per CTA: 2 planes x 48 k-pairs x 264 words (256 data + 8 pad)
#define WPLANE (48 * 264)            // 12672 words per plane
#define WWORDS (2 * WPLANE)          // 25344 words = 101376 B
// A smem image: 64 b-rows x 100 words (48 hi + 48 lo + 4 pad)
#define AWORDS (64 * 100)            // 6400 words = 25600 B
#define DSMB   ((AWORDS + WWORDS) * 4)   // 126976 B dynamic smem

// ---------------- device scratch -------------------------------------------------
__device__ __align__(128) __half g_W16[NCTA * WWORDS * 2]; // per-CTA W image (13 MB)
__device__ __align__(128) unsigned g_a16[5 * BB * 1024];   // [slot][b][512 hi w | 512 lo w]
__device__ __align__(128) float g_inp[TT * BN];            // 105 MB inputs @ w_in
__device__ __align__(128) float g_mem[BN];
__device__ __align__(128) float g_wp[BN];
__device__ __align__(128) float g_outd[2 * BN];            // spikes, double-buffer
__device__ __align__(128) float g_part[SPLITK * BN];       // split-K partials
__device__ __align__(128) float g_r[BB * NOUTC];
__device__ unsigned g_bar;

#define MMA_F16(c, a0, a1, a2, a3, b0, b1) \
    asm("mma.sync.aligned.m16n8k16.row.col.f32.f16.f16.f32 " \
        "{%0,%1,%2,%3},{%4,%5,%6,%7},{%8,%9},{%0,%1,%2,%3};" \
        : "+f"((c)[0]), "+f"((c)[1]), "+f"((c)[2]), "+f"((c)[3]) \
        : "r"(a0), "r"(a1), "r"(a2), "r"(a3), "r"(b0), "r"(b1))

// ---------------- zero state + barrier (every replay) ----------------------------
__global__ void k_init() {
    int i = blockIdx.x * 256 + threadIdx.x;
    const int st = 64 * 256;
    for (int j = i; j < BN; j += st) { g_mem[j] = 0.f; g_wp[j] = 0.f; }
    for (int j = i; j < 2 * BN; j += st) g_outd[j] = 0.f;
    for (int j = i; j < 5 * BB * 1024; j += st) g_a16[j] = 0u;
    for (int j = i; j < BB * NOUTC; j += st) g_r[j] = 0.f;
    if (i == 0) g_bar = 0u;
}

// ------- W prep: fp16 hi/lo split into per-CTA smem images [kpair][n] ------------
__global__ void k_prep(const float* __restrict__ w, const float* __restrict__ ws,
                       const float* __restrict__ dmap) {
    int i = blockIdx.x * 256 + threadIdx.x;          // over [d][e][o], 3M elems
    int eo = i & (NN * NN - 1);
    int d = i >> 20, e = eo >> 10, o = eo & (NN - 1);
    float v = dmap[i] * (ws[e] * fabsf(w[eo]));
    __half h = __float2half_rn(v);
    __half l = __float2half_rn(v - __half2float(h));
    int k = d * NN + e;                 // global k in [0,3072)
    int kbs = k / 96, kl = k % 96;
    int kp = kl >> 1, hl = k & 1;
    int ot = o >> 8, nl = o & 255;
    int bid = ot * 32 + kbs;
    long base = (long)bid * (WWORDS * 2);            // halves
    long hi = base + (long)(kp * 264 + nl) * 2 + hl;
    g_W16[hi] = h;
    g_W16[hi + WPLANE * 2] = l;
}

// ------------- input projection (unchanged fp32) ---------------------------------
__global__ __launch_bounds__(256) void k_inp(const float* __restrict__ inputs,
                                             const float* __restrict__ w_in) {
    __shared__ float A_sm[64 * 33];
    __shared__ float W_sm[32 * 64];
    const int mt = blockIdx.x >> 4;
    const int nt = blockIdx.x & 15;
    const int tid = threadIdx.x;
    const int mq = tid >> 4, nq = tid & 15;
    float acc[16];
#pragma unroll
    for (int i = 0; i < 16; i++) acc[i] = 0.f;
    for (int c0 = 0; c0 < NINC; c0 += 32) {
        int kk = tid & 31, rb = tid >> 5;
#pragma unroll
        for (int j = 0; j < 8; j++) {
            int row = rb + 8 * j;
            A_sm[row * 33 + kk] = inputs[row * (TT * NINC) + mt * NINC + c0 + kk];
        }
        int ol = tid & 63, kl = tid >> 6;
#pragma unroll
        for (int j = 0; j < 8; j++) {
            int k2 = kl + 4 * j;
            W_sm[k2 * 64 + ol] = w_in[(c0 + k2) * NN + nt * 64 + ol];
        }
        __syncthreads();
#pragma unroll
        for (int k2 = 0; k2 < 32; k2++) {
            float4 wv = *(const float4*)&W_sm[k2 * 64 + nq * 4];
            float a0 = A_sm[(mq * 4 + 0) * 33 + k2];
            float a1 = A_sm[(mq * 4 + 1) * 33 + k2];
            float a2 = A_sm[(mq * 4 + 2) * 33 + k2];
            float a3 = A_sm[(mq * 4 + 3) * 33 + k2];
            acc[0]  += a0 * wv.x; acc[1]  += a0 * wv.y; acc[2]  += a0 * wv.z; acc[3]  += a0 * wv.w;
            acc[4]  += a1 * wv.x; acc[5]  += a1 * wv.y; acc[6]  += a1 * wv.z; acc[7]  += a1 * wv.w;
            acc[8]  += a2 * wv.x; acc[9]  += a2 * wv.y; acc[10] += a2 * wv.z; acc[11] += a2 * wv.w;
            acc[12] += a3 * wv.x; acc[13] += a3 * wv.y; acc[14] += a3 * wv.z; acc[15] += a3 * wv.w;
        }
        __syncthreads();
    }
#pragma unroll
    for (int i = 0; i < 4; i++) {
        float4 v = make_float4(acc[i * 4], acc[i * 4 + 1], acc[i * 4 + 2], acc[i * 4 + 3]);
        *(float4*)&g_inp[mt * BN + (mq * 4 + i) * NN + nt * 64 + nq * 4] = v;
    }
}

// ---------------- cp.async (R13-proven machinery) --------------------------------
__device__ __forceinline__ void cpa16(void* s, const void* g) {
    unsigned a = (unsigned)__cvta_generic_to_shared(s);
    asm volatile("cp.async.cg.shared.global [%0], [%1], 16;" :: "r"(a), "l"(g));
}

// -------- grid barrier (proven R9-R15) -------------------------------------------
__device__ __forceinline__ void gbar(unsigned& target) {
    __syncthreads();
    if (threadIdx.x == 0) {
        __threadfence();
        atomicAdd(&g_bar, 1u);
        target += NCTA;
        unsigned v;
        asm volatile("ld.acquire.gpu.u32 %0, [%1];" : "=r"(v) : "l"(&g_bar) : "memory");
        while (v < target) {
            __nanosleep(32);
            asm volatile("ld.acquire.gpu.u32 %0, [%1];" : "=r"(v) : "l"(&g_bar) : "memory");
        }
    }
    __syncthreads();
}

// ---------------- persistent T-loop ----------------------------------------------
// smem: [0,6400) A image; [6400,31744) W image (resident all 400 steps)
// phase A: all 128 CTAs GEMM(t); phase B: CTAs 0..31 update(t), 32..95 readout(t-1)
__global__ __launch_bounds__(NTH, 1) void k_loop(const float* __restrict__ p,
                                                 const float* __restrict__ w_out,
                                                 float* __restrict__ out) {
    extern __shared__ unsigned dsm[];
    __shared__ float red[NTH];
    unsigned* Aw = dsm;                  // A image
    unsigned* Wp = dsm + AWORDS;         // W hi plane; lo at +WPLANE
    const int tid = threadIdx.x;
    const int bid = blockIdx.x;
    const int ot = bid >> 5, kbs = bid & 31;
    const int obase = ot * 256;
    const int lane = tid & 31, wid = tid >> 5;
    const int g = lane >> 2, ig = lane & 3;
    const int mw = wid & 1;              // 2 m-groups (32 rows)
    const int nw = wid >> 1;             // 8 n-groups (32 cols)
    unsigned target = 0;

    // -------- one-time: load resident W image into smem --------
    {
        const unsigned* wsrc = (const unsigned*)&g_W16[(long)bid * (WWORDS * 2)];
        for (int i = tid; i < WWORDS; i += NTH) Wp[i] = wsrc[i];
    }
    __syncthreads();

    for (int t = 0; t <= TT; ++t) {
        // ================= phase A: GEMM(t) =================
        if (t < TT) {
            const int s1 = (t + 4) % 5, s2 = (t + 3) % 5, s4 = (t + 1) % 5;
            // ---- stage A: 1536 x 16B cp.async (3 per thread) ----
#pragma unroll
            for (int j = 0; j < 3; j++) {
                int idx = tid + j * NTH;             // [0,1536)
                int c = idx >> 8;                    // chunk 0..5
                int r = idx & 255;
                int plane = r >> 7, b = (r >> 1) & 63, h = r & 1;
                int k0 = kbs * 96 + c * 16;
                int d = k0 >> 10, e0 = k0 & (NN - 1);
                int sl = (d == 0) ? s1 : ((d == 1) ? s2 : s4);
                const unsigned* src = &g_a16[(sl * BB + b) * 1024 + plane * 512
                                             + (e0 >> 1) + h * 4];
                unsigned* dst = &Aw[b * 100 + plane * 48 + c * 8 + h * 4];
                cpa16(dst, src);
            }
            asm volatile("cp.async.commit_group;" ::: "memory");
            asm volatile("cp.async.wait_group 0;" ::: "memory");
            __syncthreads();

            float c4[2][4][4];
#pragma unroll
            for (int mt = 0; mt < 2; mt++)
#pragma unroll
                for (int nb = 0; nb < 4; nb++)
#pragma unroll
                    for (int j = 0; j < 4; j++) c4[mt][nb][j] = 0.f;

#pragma unroll
            for (int c = 0; c < 6; c++) {
                // A fragments (hi + lo), rows mw*32 + mt*16 + {g, g+8}
                unsigned ah[2][4], al[2][4];
#pragma unroll
                for (int mt = 0; mt < 2; mt++) {
                    int r0 = mw * 32 + mt * 16 + g;
                    const unsigned* A0 = &Aw[r0 * 100 + c * 8 + ig];
                    const unsigned* A1 = &Aw[(r0 + 8) * 100 + c * 8 + ig];
                    ah[mt][0] = A0[0];  ah[mt][1] = A1[0];
                    ah[mt][2] = A0[4];  ah[mt][3] = A1[4];
                    al[mt][0] = A0[48]; al[mt][1] = A1[48];
                    al[mt][2] = A0[52]; al[mt][3] = A1[52];
                }
#pragma unroll
                for (int nb = 0; nb < 4; nb++) {
                    int col = nw * 32 + nb * 8 + g;
                    unsigned bh0 = Wp[(c * 8 + ig) * 264 + col];
                    unsigned bh1 = Wp[(c * 8 + ig + 4) * 264 + col];
                    unsigned bl0 = Wp[WPLANE + (c * 8 + ig) * 264 + col];
                    unsigned bl1 = Wp[WPLANE + (c * 8 + ig + 4) * 264 + col];
#pragma unroll
                    for (int mt = 0; mt < 2; mt++) {
                        MMA_F16(c4[mt][nb], ah[mt][0], ah[mt][1], ah[mt][2], ah[mt][3], bh0, bh1);
                        MMA_F16(c4[mt][nb], ah[mt][0], ah[mt][1], ah[mt][2], ah[mt][3], bl0, bl1);
                        MMA_F16(c4[mt][nb], al[mt][0], al[mt][1], al[mt][2], al[mt][3], bh0, bh1);
                    }
                }
            }
            // epilogue -> split-K partials
#pragma unroll
            for (int mt = 0; mt < 2; mt++)
#pragma unroll
                for (int nb = 0; nb < 4; nb++) {
                    int col = obase + nw * 32 + nb * 8 + 2 * ig;
                    int r0 = mw * 32 + mt * 16 + g;
                    *(float2*)&g_part[kbs * BN + r0 * NN + col] =
                        make_float2(c4[mt][nb][0], c4[mt][nb][1]);
                    *(float2*)&g_part[kbs * BN + (r0 + 8) * NN + col] =
                        make_float2(c4[mt][nb][2], c4[mt][nb][3]);
                }
        }
        gbar(target);

        // ================= phase B: update(t) | readout(t-1) =================
        if (bid < 32) {
            if (t < TT) {
                int i4 = (bid * NTH + tid) * 4;
                int b = i4 >> 10, nb0 = i4 & (NN - 1), sl = t % 5;
                float4 mem  = *(float4*)&g_mem[i4];
                float4 wp   = *(float4*)&g_wp[i4];
                float4 pv   = *(const float4*)&p[nb0];
                float4 inpv = *(float4*)&g_inp[t * BN + i4];
                float4 syn  = make_float4(0.f, 0.f, 0.f, 0.f);
#pragma unroll
                for (int k = 0; k < SPLITK; k++) {   // deterministic fixed-order reduce
                    float4 v = __ldcg((const float4*)&g_part[k * BN + i4]);
                    syn.x += v.x; syn.y += v.y; syn.z += v.z; syn.w += v.w;
                }
                float o0 = mem.x > 1.f ? 1.f : 0.f;
                float o1 = mem.y > 1.f ? 1.f : 0.f;
                float o2 = mem.z > 1.f ? 1.f : 0.f;
                float o3 = mem.w > 1.f ? 1.f : 0.f;

                float av[4] = { o0 * (1.f + wp.x), o1 * (1.f + wp.y),
                                o2 * (1.f + wp.z), o3 * (1.f + wp.w) };
                // fp16 hi/lo act planes, packed 2 e per word
                unsigned hw[2], lw[2];
#pragma unroll
                for (int j = 0; j < 2; j++) {
                    __half h0 = __float2half_rn(av[2 * j]);
                    __half h1 = __float2half_rn(av[2 * j + 1]);
                    __half l0 = __float2half_rn(av[2 * j] - __half2float(h0));
                    __half l1 = __float2half_rn(av[2 * j + 1] - __half2float(h1));
                    __half2 hh = __halves2half2(h0, h1);
                    __half2 ll = __halves2half2(l0, l1);
                    hw[j] = *(unsigned*)&hh;
                    lw[j] = *(unsigned*)&ll;
                }
                unsigned* arow = &g_a16[(sl * BB + b) * 1024];
                int wofs = nb0 >> 1;
                __stcg(&arow[wofs], hw[0]);
                __stcg(&arow[wofs + 1], hw[1]);
                __stcg(&arow[512 + wofs], lw[0]);
                __stcg(&arow[512 + wofs + 1], lw[1]);

                *(float4*)&g_outd[(t & 1) * BN + i4] = make_float4(o0, o1, o2, o3);

                wp.x = 0.99f * wp.x + o0 * pv.x * (1.f + (pv.x < 0.f ? wp.x : 0.f));
                wp.y = 0.99f * wp.y + o1 * pv.y * (1.f + (pv.y < 0.f ? wp.y : 0.f));
                wp.z = 0.99f * wp.z + o2 * pv.z * (1.f + (pv.z < 0.f ? wp.z : 0.f));
                wp.w = 0.99f * wp.w + o3 * pv.w * (1.f + (pv.w < 0.f ? wp.w : 0.f));

                mem.x = 0.95f * mem.x + inpv.x + syn.x - o0;
                mem.y = 0.95f * mem.y + inpv.y + syn.y - o1;
                mem.z = 0.95f * mem.z + inpv.z + syn.z - o2;
                mem.w = 0.95f * mem.w + inpv.w + syn.w - o3;

                *(float4*)&g_wp[i4]  = wp;
                *(float4*)&g_mem[i4] = mem;
            }
        } else if (bid < 96 && t > 0) {
            int b = bid - 32;
            int o = tid & 31, ch = tid >> 5;
            const float* ob = &g_outd[((t - 1) & 1) * BN + b * NN];
            float s = 0.f;
            int e0 = ch * 64;
#pragma unroll 4
            for (int e = e0; e < e0 + 64; e++)
                s += __ldcg(&ob[e]) * __ldg(&w_out[e * NOUTC + o]);
            red[tid] = s;
            __syncthreads();
            if (tid < 32) {
                float h = 0.f;
#pragma unroll
                for (int cq = 0; cq < 16; cq++) h += red[cq * 32 + tid];
                float r = 0.95f * g_r[b * NOUTC + tid] + h;
                g_r[b * NOUTC + tid] = r;
                out[b * (TT * NOUTC) + (t - 1) * NOUTC + tid] = r;
            }
            __syncthreads();
        }
        gbar(target);
    }
}

extern "C" void kernel_launch(void* const* d_in, const int* in_sizes, int n_in,
                              void* d_out, int out_size) {
    (void)in_sizes; (void)n_in; (void)out_size;
    const float* inputs = (const float*)d_in[0];
    const float* w      = (const float*)d_in[1];
    const float* w_in   = (const float*)d_in[2];
    const float* w_out  = (const float*)d_in[3];
    const float* ws     = (const float*)d_in[4];
    const float* dmap   = (const float*)d_in[5];
    const float* p      = (const float*)d_in[6];
    float* out = (float*)d_out;

    cudaFuncSetAttribute(k_loop, cudaFuncAttributeMaxDynamicSharedMemorySize,
                         DSMB);         // idempotent host call
    k_init<<<64, 256>>>();
    k_prep<<<(3 * NN * NN) / 256, 256>>>(w, ws, dmap);
    k_inp<<<TT * 16, 256>>>(inputs, w_in);
    k_loop<<<NCTA, NTH, DSMB>>>(p, w_out, out);
}

// round 17
// speedup vs baseline: 1.5840x; 1.0008x over previous
#include <cuda_runtime.h>
#include <cuda_fp16.h>
#include <math.h>

#define BB    64
#define TT    400
#define NN    1024
#define NINC  128
#define NOUTC 32
#define BN    (BB * NN)
#define SPLITK 32
#define NCTA  128
#define NTH   512
// W smem image per CTA: 2 planes x 48 k-pairs x 264 words (256 data + 8 pad)
#define WPLANE (48 * 264)            // 12672 words per plane
#define WWORDS (2 * WPLANE)          // 25344 words = 101376 B
// A smem image: 64 b-rows x 100 words (48 hi + 48 lo + 4 pad)
#define AWORDS (64 * 100)            // 6400 words = 25600 B
#define DSMB   ((AWORDS + WWORDS) * 4)   // 126976 B dynamic smem

// ---------------- device scratch -------------------------------------------------
__device__ __align__(128) __half g_W16[NCTA * WWORDS * 2]; // per-CTA W image (13 MB)
__device__ __align__(128) unsigned g_a16[5 * BB * 1024];   // [slot][b][512 hi w | 512 lo w]
__device__ __align__(128) float g_inp[TT * BN];            // 105 MB inputs @ w_in
__device__ __align__(128) float g_mem[BN];
__device__ __align__(128) float g_wp[BN];
__device__ __align__(128) float g_outd[2 * BN];            // spikes, double-buffer
__device__ __align__(128) float g_part[SPLITK * BN];       // split-K partials
__device__ __align__(128) float g_r[BB * NOUTC];
__device__ unsigned g_bar;

#define MMA_F16(c, a0, a1, a2, a3, b0, b1) \
    asm("mma.sync.aligned.m16n8k16.row.col.f32.f16.f16.f32 " \
        "{%0,%1,%2,%3},{%4,%5,%6,%7},{%8,%9},{%0,%1,%2,%3};" \
        : "+f"((c)[0]), "+f"((c)[1]), "+f"((c)[2]), "+f"((c)[3]) \
        : "r"(a0), "r"(a1), "r"(a2), "r"(a3), "r"(b0), "r"(b1))

#define LDSM_X4(r, addr) \
    asm volatile("ldmatrix.sync.aligned.m8n8.x4.shared.b16 {%0,%1,%2,%3}, [%4];" \
        : "=r"((r)[0]), "=r"((r)[1]), "=r"((r)[2]), "=r"((r)[3]) : "r"(addr))

// ---------------- zero state + barrier (every replay) ----------------------------
__global__ void k_init() {
    int i = blockIdx.x * 256 + threadIdx.x;
    const int st = 64 * 256;
    for (int j = i; j < BN; j += st) { g_mem[j] = 0.f; g_wp[j] = 0.f; }
    for (int j = i; j < 2 * BN; j += st) g_outd[j] = 0.f;
    for (int j = i; j < 5 * BB * 1024; j += st) g_a16[j] = 0u;
    for (int j = i; j < BB * NOUTC; j += st) g_r[j] = 0.f;
    if (i == 0) g_bar = 0u;
}

// ------- W prep: fp16 hi/lo split into per-CTA smem images [kpair][n] ------------
__global__ void k_prep(const float* __restrict__ w, const float* __restrict__ ws,
                       const float* __restrict__ dmap) {
    int i = blockIdx.x * 256 + threadIdx.x;          // over [d][e][o], 3M elems
    int eo = i & (NN * NN - 1);
    int d = i >> 20, e = eo >> 10, o = eo & (NN - 1);
    float v = dmap[i] * (ws[e] * fabsf(w[eo]));
    __half h = __float2half_rn(v);
    __half l = __float2half_rn(v - __half2float(h));
    int k = d * NN + e;                 // global k in [0,3072)
    int kbs = k / 96, kl = k % 96;
    int kp = kl >> 1, hl = k & 1;
    int ot = o >> 8, nl = o & 255;
    int bid = ot * 32 + kbs;
    long base = (long)bid * (WWORDS * 2);            // halves
    long hi = base + (long)(kp * 264 + nl) * 2 + hl;
    g_W16[hi] = h;
    g_W16[hi + WPLANE * 2] = l;
}

// ------------- input projection (unchanged fp32) ---------------------------------
__global__ __launch_bounds__(256) void k_inp(const float* __restrict__ inputs,
                                             const float* __restrict__ w_in) {
    __shared__ float A_sm[64 * 33];
    __shared__ float W_sm[32 * 64];
    const int mt = blockIdx.x >> 4;
    const int nt = blockIdx.x & 15;
    const int tid = threadIdx.x;
    const int mq = tid >> 4, nq = tid & 15;
    float acc[16];
#pragma unroll
    for (int i = 0; i < 16; i++) acc[i] = 0.f;
    for (int c0 = 0; c0 < NINC; c0 += 32) {
        int kk = tid & 31, rb = tid >> 5;
#pragma unroll
        for (int j = 0; j < 8; j++) {
            int row = rb + 8 * j;
            A_sm[row * 33 + kk] = inputs[row * (TT * NINC) + mt * NINC + c0 + kk];
        }
        int ol = tid & 63, kl = tid >> 6;
#pragma unroll
        for (int j = 0; j < 8; j++) {
            int k2 = kl + 4 * j;
            W_sm[k2 * 64 + ol] = w_in[(c0 + k2) * NN + nt * 64 + ol];
        }
        __syncthreads();
#pragma unroll
        for (int k2 = 0; k2 < 32; k2++) {
            float4 wv = *(const float4*)&W_sm[k2 * 64 + nq * 4];
            float a0 = A_sm[(mq * 4 + 0) * 33 + k2];
            float a1 = A_sm[(mq * 4 + 1) * 33 + k2];
            float a2 = A_sm[(mq * 4 + 2) * 33 + k2];
            float a3 = A_sm[(mq * 4 + 3) * 33 + k2];
            acc[0]  += a0 * wv.x; acc[1]  += a0 * wv.y; acc[2]  += a0 * wv.z; acc[3]  += a0 * wv.w;
            acc[4]  += a1 * wv.x; acc[5]  += a1 * wv.y; acc[6]  += a1 * wv.z; acc[7]  += a1 * wv.w;
            acc[8]  += a2 * wv.x; acc[9]  += a2 * wv.y; acc[10] += a2 * wv.z; acc[11] += a2 * wv.w;
            acc[12] += a3 * wv.x; acc[13] += a3 * wv.y; acc[14] += a3 * wv.z; acc[15] += a3 * wv.w;
        }
        __syncthreads();
    }
#pragma unroll
    for (int i = 0; i < 4; i++) {
        float4 v = make_float4(acc[i * 4], acc[i * 4 + 1], acc[i * 4 + 2], acc[i * 4 + 3]);
        *(float4*)&g_inp[mt * BN + (mq * 4 + i) * NN + nt * 64 + nq * 4] = v;
    }
}

// ---------------- cp.async -------------------------------------------------------
__device__ __forceinline__ void cpa16(void* s, const void* g) {
    unsigned a = (unsigned)__cvta_generic_to_shared(s);
    asm volatile("cp.async.cg.shared.global [%0], [%1], 16;" :: "r"(a), "l"(g));
}

// -------- grid barrier (proven R9-R16) -------------------------------------------
__device__ __forceinline__ void gbar(unsigned& target) {
    __syncthreads();
    if (threadIdx.x == 0) {
        __threadfence();
        atomicAdd(&g_bar, 1u);
        target += NCTA;
        unsigned v;
        asm volatile("ld.acquire.gpu.u32 %0, [%1];" : "=r"(v) : "l"(&g_bar) : "memory");
        while (v < target) {
            __nanosleep(32);
            asm volatile("ld.acquire.gpu.u32 %0, [%1];" : "=r"(v) : "l"(&g_bar) : "memory");
        }
    }
    __syncthreads();
}

// ---------------- persistent T-loop ----------------------------------------------
// smem: [0,6400) A image; [6400,31744) W image (resident all 400 steps)
// phase A: all 128 CTAs GEMM(t); phase B: CTAs 0..63 update(t), 64..127 readout(t-1)
__global__ __launch_bounds__(NTH, 1) void k_loop(const float* __restrict__ p,
                                                 const float* __restrict__ w_out,
                                                 float* __restrict__ out) {
    extern __shared__ unsigned dsm[];
    __shared__ float red[NTH];
    unsigned* Aw = dsm;                  // A image
    unsigned* Wp = dsm + AWORDS;         // W hi plane; lo at +WPLANE
    const int tid = threadIdx.x;
    const int bid = blockIdx.x;
    const int ot = bid >> 5, kbs = bid & 31;
    const int obase = ot * 256;
    const int lane = tid & 31, wid = tid >> 5;
    const int g = lane >> 2, ig = lane & 3;
    const int mw = wid & 1;              // 2 m-groups (32 rows)
    const int nw = wid >> 1;             // 8 n-groups (32 cols)
    const int rowsel = lane & 15;        // ldmatrix.x4 lane->row
    const int kwsel = (lane >> 4) * 4;   // ldmatrix.x4 lane->k-word half
    unsigned target = 0;

    // -------- one-time: load resident W image into smem --------
    {
        const unsigned* wsrc = (const unsigned*)&g_W16[(long)bid * (WWORDS * 2)];
        for (int i = tid; i < WWORDS; i += NTH) Wp[i] = wsrc[i];
    }
    __syncthreads();

    for (int t = 0; t <= TT; ++t) {
        // ================= phase A: GEMM(t) =================
        if (t < TT) {
            const int s1 = (t + 4) % 5, s2 = (t + 3) % 5, s4 = (t + 1) % 5;
            // ---- stage A: 3 commit groups, chunk pairs {0,1},{2,3},{4,5} ----
#pragma unroll
            for (int j = 0; j < 3; j++) {
                int idx = tid + j * NTH;             // [0,1536)
                int c = idx >> 8;                    // chunk 0..5
                int r = idx & 255;
                int plane = r >> 7, b = (r >> 1) & 63, h = r & 1;
                int k0 = kbs * 96 + c * 16;
                int d = k0 >> 10, e0 = k0 & (NN - 1);
                int sl = (d == 0) ? s1 : ((d == 1) ? s2 : s4);
                const unsigned* src = &g_a16[(sl * BB + b) * 1024 + plane * 512
                                             + (e0 >> 1) + h * 4];
                unsigned* dst = &Aw[b * 100 + plane * 48 + c * 8 + h * 4];
                cpa16(dst, src);
                asm volatile("cp.async.commit_group;" ::: "memory");
            }

            float c4[2][4][4];
#pragma unroll
            for (int mt = 0; mt < 2; mt++)
#pragma unroll
                for (int nb = 0; nb < 4; nb++)
#pragma unroll
                    for (int j = 0; j < 4; j++) c4[mt][nb][j] = 0.f;

#pragma unroll
            for (int c = 0; c < 6; c++) {
                if (c == 0) { asm volatile("cp.async.wait_group 2;" ::: "memory"); __syncthreads(); }
                else if (c == 2) { asm volatile("cp.async.wait_group 1;" ::: "memory"); __syncthreads(); }
                else if (c == 4) { asm volatile("cp.async.wait_group 0;" ::: "memory"); __syncthreads(); }
                // A fragments via ldmatrix.x4 (hi + lo planes)
                unsigned ah[2][4], al[2][4];
#pragma unroll
                for (int mt = 0; mt < 2; mt++) {
                    int rbase = (mw * 32 + mt * 16 + rowsel) * 100 + c * 8 + kwsel;
                    unsigned sah = (unsigned)__cvta_generic_to_shared(&Aw[rbase]);
                    LDSM_X4(ah[mt], sah);
                    LDSM_X4(al[mt], sah + 48 * 4);
                }
#pragma unroll
                for (int nb = 0; nb < 4; nb++) {
                    int col = nw * 32 + nb * 8 + g;
                    unsigned bh0 = Wp[(c * 8 + ig) * 264 + col];
                    unsigned bh1 = Wp[(c * 8 + ig + 4) * 264 + col];
                    unsigned bl0 = Wp[WPLANE + (c * 8 + ig) * 264 + col];
                    unsigned bl1 = Wp[WPLANE + (c * 8 + ig + 4) * 264 + col];
#pragma unroll
                    for (int mt = 0; mt < 2; mt++) {
                        MMA_F16(c4[mt][nb], ah[mt][0], ah[mt][1], ah[mt][2], ah[mt][3], bh0, bh1);
                        MMA_F16(c4[mt][nb], ah[mt][0], ah[mt][1], ah[mt][2], ah[mt][3], bl0, bl1);
                        MMA_F16(c4[mt][nb], al[mt][0], al[mt][1], al[mt][2], al[mt][3], bh0, bh1);
                    }
                }
            }
            // epilogue -> split-K partials
#pragma unroll
            for (int mt = 0; mt < 2; mt++)
#pragma unroll
                for (int nb = 0; nb < 4; nb++) {
                    int col = obase + nw * 32 + nb * 8 + 2 * ig;
                    int r0 = mw * 32 + mt * 16 + g;
                    *(float2*)&g_part[kbs * BN + r0 * NN + col] =
                        make_float2(c4[mt][nb][0], c4[mt][nb][1]);
                    *(float2*)&g_part[kbs * BN + (r0 + 8) * NN + col] =
                        make_float2(c4[mt][nb][2], c4[mt][nb][3]);
                }
        }
        gbar(target);

        // ================= phase B: update(t) | readout(t-1) =================
        if (bid < 64) {
            if (t < TT) {
                int i2 = (bid * NTH + tid) * 2;          // 2 elems per thread
                int b = i2 >> 10, nb0 = i2 & (NN - 1), sl = t % 5;
                float2 mem  = *(float2*)&g_mem[i2];
                float2 wp   = *(float2*)&g_wp[i2];
                float2 pv   = *(const float2*)&p[nb0];
                float2 inpv = *(float2*)&g_inp[t * BN + i2];
                float2 syn  = make_float2(0.f, 0.f);
#pragma unroll
                for (int k = 0; k < SPLITK; k++) {   // deterministic fixed-order reduce
                    float2 v = __ldcg((const float2*)&g_part[k * BN + i2]);
                    syn.x += v.x; syn.y += v.y;
                }
                float o0 = mem.x > 1.f ? 1.f : 0.f;
                float o1 = mem.y > 1.f ? 1.f : 0.f;

                float a0 = o0 * (1.f + wp.x);
                float a1 = o1 * (1.f + wp.y);
                // fp16 hi/lo act planes, packed 2 e per word
                __half h0 = __float2half_rn(a0);
                __half h1 = __float2half_rn(a1);
                __half l0 = __float2half_rn(a0 - __half2float(h0));
                __half l1 = __float2half_rn(a1 - __half2float(h1));
                __half2 hh = __halves2half2(h0, h1);
                __half2 ll = __halves2half2(l0, l1);
                unsigned* arow = &g_a16[(sl * BB + b) * 1024];
                int wofs = nb0 >> 1;
                __stcg(&arow[wofs], *(unsigned*)&hh);
                __stcg(&arow[512 + wofs], *(unsigned*)&ll);

                *(float2*)&g_outd[(t & 1) * BN + i2] = make_float2(o0, o1);

                wp.x = 0.99f * wp.x + o0 * pv.x * (1.f + (pv.x < 0.f ? wp.x : 0.f));
                wp.y = 0.99f * wp.y + o1 * pv.y * (1.f + (pv.y < 0.f ? wp.y : 0.f));

                mem.x = 0.95f * mem.x + inpv.x + syn.x - o0;
                mem.y = 0.95f * mem.y + inpv.y + syn.y - o1;

                *(float2*)&g_wp[i2]  = wp;
                *(float2*)&g_mem[i2] = mem;
            }
        } else if (t > 0) {
            int b = bid - 64;
            int o = tid & 31, ch = tid >> 5;
            const float* ob = &g_outd[((t - 1) & 1) * BN + b * NN];
            float s = 0.f;
            int e0 = ch * 64;
#pragma unroll 4
            for (int e = e0; e < e0 + 64; e++)
                s += __ldcg(&ob[e]) * __ldg(&w_out[e * NOUTC + o]);
            red[tid] = s;
            __syncthreads();
            if (tid < 32) {
                float h = 0.f;
#pragma unroll
                for (int cq = 0; cq < 16; cq++) h += red[cq * 32 + tid];
                float r = 0.95f * g_r[b * NOUTC + tid] + h;
                g_r[b * NOUTC + tid] = r;
                out[b * (TT * NOUTC) + (t - 1) * NOUTC + tid] = r;
            }
            __syncthreads();
        }
        gbar(target);
    }
}

extern "C" void kernel_launch(void* const* d_in, const int* in_sizes, int n_in,
                              void* d_out, int out_size) {
    (void)in_sizes; (void)n_in; (void)out_size;
    const float* inputs = (const float*)d_in[0];
    const float* w      = (const float*)d_in[1];
    const float* w_in   = (const float*)d_in[2];
    const float* w_out  = (const float*)d_in[3];
    const float* ws     = (const float*)d_in[4];
    const float* dmap   = (const float*)d_in[5];
    const float* p      = (const float*)d_in[6];
    float* out = (float*)d_out;

    cudaFuncSetAttribute(k_loop, cudaFuncAttributeMaxDynamicSharedMemorySize,
                         DSMB);         // idempotent host call
    k_init<<<64, 256>>>();
    k_prep<<<(3 * NN * NN) / 256, 256>>>(w, ws, dmap);
    k_inp<<<TT * 16, 256>>>(inputs, w_in);
    k_loop<<<NCTA, NTH, DSMB>>>(p, w_out, out);
}